// round 16
// baseline (speedup 1.0000x reference)
#include <cuda_runtime.h>
#include <cuda_bf16.h>

// MaskedPooling: out[b,d] = sum_t x[b,t,d]*keep[b,t] / sum_t keep[b,t]
// x: [32,4096,512] f32, mask: [32,4096] int32 (nonzero = excluded).
// R16: gap-bridging weighted reads. SM-side shaping (occ/MLP/pipeline/TMA/
// burst layout, R4-R15) never moved DRAM off ~60% -> the 50%-punctured access
// set itself (4KB avg contiguous runs) is the limiter. Now ALSO read masked
// rows whose both neighbors are kept (weight 0 via FFMA): read-set 62.5% of
// rows, contiguous spans ~9KB (breaks only at masked-runs>=2). Mainloop =
// R10's depth-1 batch-4 pipeline, FFMA by per-row weight from smem; read-list
// padded to x4 with weight-0 entries (no tail loop). Fused last-CTA finalize.

#define B_DIM 32
#define T_DIM 4096
#define D_DIM 512
#define S_SPLIT 32
#define ROWS (T_DIM / S_SPLIT)   // 128
#define TPB 128                  // 128 threads * float4 = 512 floats = D
#define DSTRIDE (D_DIM / 4)      // 128 float4 per row
#define ROW_BYTES (D_DIM * 4)    // 2048

__device__ float g_partial[B_DIM * S_SPLIT * D_DIM];  // 2 MB scratch
__device__ float g_count[B_DIM * S_SPLIT];
__device__ int   g_sem[B_DIM];                        // zero-init; self-resetting

#define ACC4(A, V) do { (A).x += (V).x; (A).y += (V).y; (A).z += (V).z; (A).w += (V).w; } while (0)
#define FMA4(A, W, V) do { \
    (A).x = fmaf((W), (V).x, (A).x); (A).y = fmaf((W), (V).y, (A).y); \
    (A).z = fmaf((W), (V).z, (A).z); (A).w = fmaf((W), (V).w, (A).w); } while (0)

__global__ __launch_bounds__(TPB, 7) void mp_fused_kernel(
    const float* __restrict__ x, const int* __restrict__ mask,
    float* __restrict__ out) {
    const int s = blockIdx.x;   // T-chunk
    const int b = blockIdx.y;   // batch
    const int tid = threadIdx.x;
    const int lane = tid & 31;
    const int wid = tid >> 5;
    const int t0 = s * ROWS;

    __shared__ int m[ROWS];
    __shared__ int2 rwbuf[ROWS];     // {byte offset, weight bits} per read row
    __shared__ int rcnt[5];          // read-flag warp counts -> exclusive scan
    __shared__ int kcnt[4];          // kept-flag warp counts
    __shared__ int nkeepS;
    __shared__ bool isLast;

    // stage mask chunk (128 int32 = 512 B)
    if (tid < ROWS / 4) {
        reinterpret_cast<int4*>(m)[tid] =
            reinterpret_cast<const int4*>(mask + b * T_DIM + t0)[tid];
    }
    __syncthreads();

    // flags: kept, and read = kept OR isolated-masked (both neighbors kept)
    const bool kflag = (m[tid] == 0);
    const bool rflag = kflag ||
        ((tid > 0) && (tid + 1 < ROWS) && (m[tid - 1] == 0) && (m[tid + 1] == 0));
    unsigned rbal = __ballot_sync(0xffffffffu, rflag);
    unsigned kbal = __ballot_sync(0xffffffffu, kflag);
    if (lane == 0) { rcnt[wid] = __popc(rbal); kcnt[wid] = __popc(kbal); }
    __syncthreads();
    if (tid == 0) {
        int sum = 0, ks = 0;
        #pragma unroll
        for (int j = 0; j < 4; j++) {
            int c = rcnt[j]; rcnt[j] = sum; sum += c;
            ks += kcnt[j];
        }
        rcnt[4] = sum;
        nkeepS = ks;
    }
    __syncthreads();
    const int nread = rcnt[4];
    const int npad = (nread + 3) & ~3;
    if (rflag) {
        int pos = rcnt[wid] + __popc(rbal & ((1u << lane) - 1u));
        rwbuf[pos] = make_int2(tid * ROW_BYTES, kflag ? 0x3F800000 : 0);
    }
    // pad read-list to multiple of 4 with weight-0 entries (re-read row 0)
    if (tid >= nread && tid < npad) rwbuf[tid] = make_int2(0, 0);
    __syncthreads();

    const char* xbase = reinterpret_cast<const char*>(
        x + ((size_t)b * T_DIM + t0) * D_DIM) + tid * 16;

    float4 acc0 = make_float4(0.f, 0.f, 0.f, 0.f);
    float4 acc1 = make_float4(0.f, 0.f, 0.f, 0.f);

    // depth-1 batch-4 software pipeline (R10) with per-row FFMA weights
    if (npad >= 8) {
        int2 o0 = rwbuf[0], o1 = rwbuf[1], o2 = rwbuf[2], o3 = rwbuf[3];
        float4 b0 = __ldcs(reinterpret_cast<const float4*>(xbase + o0.x));
        float4 b1 = __ldcs(reinterpret_cast<const float4*>(xbase + o1.x));
        float4 b2 = __ldcs(reinterpret_cast<const float4*>(xbase + o2.x));
        float4 b3 = __ldcs(reinterpret_cast<const float4*>(xbase + o3.x));
        for (int i = 4; i + 4 <= npad; i += 4) {
            int2 p0 = rwbuf[i], p1 = rwbuf[i + 1], p2 = rwbuf[i + 2], p3 = rwbuf[i + 3];
            float4 n0 = __ldcs(reinterpret_cast<const float4*>(xbase + p0.x));
            float4 n1 = __ldcs(reinterpret_cast<const float4*>(xbase + p1.x));
            float4 n2 = __ldcs(reinterpret_cast<const float4*>(xbase + p2.x));
            float4 n3 = __ldcs(reinterpret_cast<const float4*>(xbase + p3.x));
            FMA4(acc0, __int_as_float(o0.y), b0);
            FMA4(acc1, __int_as_float(o1.y), b1);
            FMA4(acc0, __int_as_float(o2.y), b2);
            FMA4(acc1, __int_as_float(o3.y), b3);
            o0 = p0; o1 = p1; o2 = p2; o3 = p3;
            b0 = n0; b1 = n1; b2 = n2; b3 = n3;
        }
        FMA4(acc0, __int_as_float(o0.y), b0);
        FMA4(acc1, __int_as_float(o1.y), b1);
        FMA4(acc0, __int_as_float(o2.y), b2);
        FMA4(acc1, __int_as_float(o3.y), b3);
    } else {
        for (int i = 0; i < npad; i++) {
            int2 o = rwbuf[i];
            float4 v = __ldcs(reinterpret_cast<const float4*>(xbase + o.x));
            FMA4(acc0, __int_as_float(o.y), v);
        }
    }
    ACC4(acc0, acc1);

    reinterpret_cast<float4*>(g_partial)[(size_t)(b * S_SPLIT + s) * DSTRIDE + tid] = acc0;
    if (tid == 0) g_count[b * S_SPLIT + s] = (float)nkeepS;

    // ALL warps must finish partial stores before this CTA arrives.
    __syncthreads();
    __threadfence();
    if (tid == 0) {
        int v = atomicAdd(&g_sem[b], 1);
        isLast = (v == S_SPLIT - 1);
    }
    __syncthreads();

    if (isLast) {
        float denom = 0.f;
        #pragma unroll 8
        for (int ss = 0; ss < S_SPLIT; ss++) denom += g_count[b * S_SPLIT + ss];

        float4 r0 = make_float4(0.f, 0.f, 0.f, 0.f);
        float4 r1 = make_float4(0.f, 0.f, 0.f, 0.f);
        const float4* gp = reinterpret_cast<const float4*>(g_partial);
        #pragma unroll 8
        for (int ss = 0; ss < S_SPLIT; ss += 2) {
            float4 v0 = gp[(size_t)(b * S_SPLIT + ss) * DSTRIDE + tid];
            float4 v1 = gp[(size_t)(b * S_SPLIT + ss + 1) * DSTRIDE + tid];
            ACC4(r0, v0); ACC4(r1, v1);
        }
        ACC4(r0, r1);
        float inv = 1.f / denom;
        r0.x *= inv; r0.y *= inv; r0.z *= inv; r0.w *= inv;
        reinterpret_cast<float4*>(out)[(size_t)b * DSTRIDE + tid] = r0;

        if (tid == 0) g_sem[b] = 0;  // reset for next graph replay
    }
}

extern "C" void kernel_launch(void* const* d_in, const int* in_sizes, int n_in,
                              void* d_out, int out_size) {
    const float* x = (const float*)d_in[0];
    const int* mask = (const int*)d_in[1];
    float* out = (float*)d_out;

    dim3 grid(S_SPLIT, B_DIM);
    mp_fused_kernel<<<grid, TPB>>>(x, mask, out);
}